// round 1
// baseline (speedup 1.0000x reference)
#include <cuda_runtime.h>
#include <math.h>

// Problem constants
// B=512, L=128, DIM=100, PDIM=25, WIN=3, FEAT=350, K=3*350=1050, FNUM=256, LAB=19
// Output: wo (512*256) then WL (19*256) = 135936 floats

// ---------------- scratch (static device arrays; no allocations allowed) ----
__device__ float g_Rpad[512 * 130 * 350];   // padded R: rows [b][0..129], row 0 and 129 are zero
__device__ float g_Wt[1050 * 256];          // conv weights transposed: Wt[k][f]
__device__ float g_Rc[512 * 128 * 256];     // Rc[b*128+l][f] = tanh(conv + bias)

// ---------------------------------------------------------------------------
// Kernel A: gather embeddings, span means, dual softmax attention, build R
// one block per batch element, 256 threads
// dynamic smem layout (floats):
//   we   [128][101]  : 12928
//   emb0 [100]
//   l1   [100]
//   l2   [100]
//   sc1  [128]
//   sc2  [128]
//   ine  [128]
//   ids/q1/q2 as int : 384
// total = 13996 floats = 55984 bytes
// ---------------------------------------------------------------------------
__global__ void prep_kernel(const int* __restrict__ inputs,
                            const int* __restrict__ e1s_, const int* __restrict__ e1e_,
                            const int* __restrict__ e2s_, const int* __restrict__ e2e_,
                            const int* __restrict__ p1, const int* __restrict__ p2,
                            const float* __restrict__ emb,
                            const float* __restrict__ pos1, const float* __restrict__ pos2)
{
    extern __shared__ float sm[];
    float* we   = sm;                   // [128][101]
    float* emb0 = sm + 12928;
    float* l1   = emb0 + 100;
    float* l2   = l1 + 100;
    float* sc1  = l2 + 100;
    float* sc2  = sc1 + 128;
    float* ine  = sc2 + 128;
    int*   ids  = (int*)(ine + 128);
    int*   q1   = ids + 128;
    int*   q2   = q1 + 128;
    __shared__ float m1s, S1s, m2s, S2s;

    const int b = blockIdx.x;
    const int tid = threadIdx.x;

    if (tid < 128) {
        ids[tid] = inputs[b * 128 + tid];
        q1[tid]  = p1[b * 128 + tid];
        q2[tid]  = p2[b * 128 + tid];
    } else if (tid < 228) {
        emb0[tid - 128] = emb[tid - 128];   // emb row 0 (pad token)
    }
    __syncthreads();

    // gather we[l][d] = emb[ids[l]][d]
    for (int i = tid; i < 128 * 100; i += 256) {
        int l = i / 100;
        int d = i - l * 100;
        we[l * 101 + d] = emb[(long long)ids[l] * 100 + d];
    }
    __syncthreads();

    // span means
    if (tid < 100) {
        int s1i = e1s_[b], e1i = e1e_[b];
        int s2i = e2s_[b], e2i = e2e_[b];
        float a = 0.f, c = 0.f;
        for (int l = s1i; l <= e1i; ++l) a += we[l * 101 + tid];
        for (int l = s2i; l <= e2i; ++l) c += we[l * 101 + tid];
        l1[tid] = a / (float)(e1i - s1i + 1);
        l2[tid] = c / (float)(e2i - s2i + 1);
    }
    __syncthreads();

    // scores s1, s2
    if (tid < 128) {
        float a = 0.f, c = 0.f;
        const float* w = we + tid * 101;
        #pragma unroll 4
        for (int d = 0; d < 100; ++d) { a += w[d] * l1[d]; c += w[d] * l2[d]; }
        sc1[tid] = a; sc2[tid] = c;
    }
    __syncthreads();

    // softmax reductions (warp0 -> sc1, warp1 -> sc2)
    if (tid < 64) {
        const float* sc = (tid < 32) ? sc1 : sc2;
        int lane = tid & 31;
        float m = -1e30f;
        for (int l = lane; l < 128; l += 32) m = fmaxf(m, sc[l]);
        for (int o = 16; o; o >>= 1) m = fmaxf(m, __shfl_xor_sync(0xffffffffu, m, o));
        float s = 0.f;
        for (int l = lane; l < 128; l += 32) s += expf(sc[l] - m);
        for (int o = 16; o; o >>= 1) s += __shfl_xor_sync(0xffffffffu, s, o);
        if (lane == 0) {
            if (tid < 32) { m1s = m; S1s = s; } else { m2s = m; S2s = s; }
        }
    }
    __syncthreads();

    if (tid < 128)
        ine[tid] = 0.5f * (expf(sc1[tid] - m1s) / S1s + expf(sc2[tid] - m2s) / S2s);
    __syncthreads();

    // write R (padded row l+1), R[l][0:300]=window embeds, [300:325]=pos1, [325:350]=pos2, all * in_e
    float* rb = g_Rpad + ((size_t)b * 130 + 1) * 350;
    for (int i = tid; i < 128 * 350; i += 256) {
        int l = i / 350;
        int d = i - l * 350;
        float s = ine[l];
        float v;
        if (d < 300) {
            if (l == 0) {
                v = 0.f;                      // WF[:,0] = 0
            } else {
                int j = d / 100;
                int dd = d - j * 100;
                int lw = l - 1 + j;           // 0..128
                v = (lw < 128) ? we[lw * 101 + dd] : emb0[dd];
                v *= s;
            }
        } else if (d < 325) {
            v = pos1[q1[l] * 25 + (d - 300)] * s;
        } else {
            v = pos2[q2[l] * 25 + (d - 325)] * s;
        }
        rb[(size_t)l * 350 + d] = v;
    }
    // zero the two padding rows for this batch
    for (int d = tid; d < 350; d += 256) {
        g_Rpad[((size_t)b * 130) * 350 + d] = 0.f;
        g_Rpad[((size_t)b * 130 + 129) * 350 + d] = 0.f;
    }
}

// ---------------------------------------------------------------------------
// Kernel W: transpose conv weights to K-major Wt[k][f] = conv_w[f*1050 + k]
// ---------------------------------------------------------------------------
__global__ void wt_kernel(const float* __restrict__ convw)
{
    int k = blockIdx.x;       // 0..1049
    int f = threadIdx.x;      // 0..255
    g_Wt[(size_t)k * 256 + f] = convw[(size_t)f * 1050 + k];
}

// ---------------------------------------------------------------------------
// Kernel B: conv as GEMM + bias + tanh
// C[m=b*128+l][f] = tanh(bias[f] + sum_{k<1050} Rpad[b][l + k/350][k%350-ish] * Wt[k][f])
// A row for (b,l) is the contiguous 1050-float slice starting at padded row l.
// Tile: BM=128 (one batch row block = one b), BN=64, BK=16; 256 thr, 8x4/thread
// ---------------------------------------------------------------------------
__global__ __launch_bounds__(256) void conv_gemm_kernel(const float* __restrict__ convb)
{
    __shared__ float As[128][20];   // [m][k], padded
    __shared__ float Bs[16][64];    // [k][n]
    const int bx = blockIdx.x;      // n-tile 0..3
    const int by = blockIdx.y;      // b 0..511
    const int tid = threadIdx.x;
    const int tx = tid & 15;        // n
    const int ty = tid >> 4;        // m
    const float* Ab = g_Rpad + (size_t)by * 130 * 350;  // row l => offset l*350
    const float* Bt = g_Wt + bx * 64;

    float acc[8][4];
    #pragma unroll
    for (int i = 0; i < 8; ++i)
        #pragma unroll
        for (int j = 0; j < 4; ++j) acc[i][j] = 0.f;

    for (int kt = 0; kt < 66; ++kt) {
        const int k0 = kt * 16;
        #pragma unroll
        for (int p = 0; p < 4; ++p) {
            int i = tid + p * 256;          // 0..1023
            int row = i >> 3;               // 0..127
            int kq = (i & 7) << 1;          // even 0..14
            int kg = k0 + kq;
            float2 v;
            if (kg < 1050) v = *(const float2*)(Ab + (size_t)row * 350 + kg);
            else           v = make_float2(0.f, 0.f);
            As[row][kq]     = v.x;
            As[row][kq + 1] = v.y;
        }
        #pragma unroll
        for (int p = 0; p < 4; ++p) {
            int i = tid + p * 256;          // 0..1023
            int kk = i >> 6;                // 0..15
            int n  = i & 63;
            int kg = k0 + kk;
            Bs[kk][n] = (kg < 1050) ? Bt[(size_t)kg * 256 + n] : 0.f;
        }
        __syncthreads();
        #pragma unroll
        for (int kk = 0; kk < 16; ++kk) {
            float a[8];
            #pragma unroll
            for (int i = 0; i < 8; ++i) a[i] = As[ty * 8 + i][kk];
            const float4 bv = *(const float4*)&Bs[kk][tx * 4];
            #pragma unroll
            for (int i = 0; i < 8; ++i) {
                acc[i][0] += a[i] * bv.x;
                acc[i][1] += a[i] * bv.y;
                acc[i][2] += a[i] * bv.z;
                acc[i][3] += a[i] * bv.w;
            }
        }
        __syncthreads();
    }

    const int f0 = bx * 64 + tx * 4;
    const float b0 = convb[f0], b1 = convb[f0 + 1], b2 = convb[f0 + 2], b3 = convb[f0 + 3];
    const int mbase = by * 128 + ty * 8;
    #pragma unroll
    for (int i = 0; i < 8; ++i) {
        float4 o;
        o.x = tanhf(acc[i][0] + b0);
        o.y = tanhf(acc[i][1] + b1);
        o.z = tanhf(acc[i][2] + b2);
        o.w = tanhf(acc[i][3] + b3);
        *(float4*)&g_Rc[(size_t)(mbase + i) * 256 + f0] = o;
    }
}

// ---------------------------------------------------------------------------
// Kernel C: T = Rc·U (LAB=19), G = T·WL, softmax over L per g, wo = max_l Rc*G_
// one block per b, 256 threads, dynamic smem:
//   Rc_s [128][257] : 32896
//   T    [128][20]  : 2560
//   Us   [256*19]   : 4864
//   WLs  [19*256]   : 4864
// total 45184 floats = 180736 bytes
// ---------------------------------------------------------------------------
__global__ __launch_bounds__(256) void head_kernel(const float* __restrict__ U,
                                                   const float* __restrict__ WL,
                                                   float* __restrict__ out)
{
    extern __shared__ float sm[];
    float* Rc_s = sm;                    // [l][f] padded to 257
    float* T    = sm + 128 * 257;        // [l][c] padded to 20
    float* Us   = T + 128 * 20;          // [f*19+c]
    float* WLs  = Us + 4864;             // [c*256+g]

    const int b = blockIdx.x;
    const int tid = threadIdx.x;

    const float* rc = g_Rc + (size_t)b * 128 * 256;
    for (int i = tid; i < 128 * 64; i += 256) {   // 128*256/4 float4 loads
        int l = i >> 6;
        int f = (i & 63) << 2;
        float4 v = *(const float4*)(rc + (size_t)l * 256 + f);
        float* dst = Rc_s + l * 257 + f;
        dst[0] = v.x; dst[1] = v.y; dst[2] = v.z; dst[3] = v.w;
    }
    for (int i = tid; i < 4864; i += 256) {
        Us[i]  = U[i];
        WLs[i] = WL[i];
    }
    __syncthreads();

    // T[l][c] = sum_f Rc_s[l][f] * U[f][c]
    for (int t = tid; t < 128 * 19; t += 256) {
        int l = t / 19;
        int c = t - l * 19;
        const float* r = Rc_s + l * 257;
        float s = 0.f;
        #pragma unroll 4
        for (int f = 0; f < 256; ++f) s += r[f] * Us[f * 19 + c];
        T[l * 20 + c] = s;
    }
    __syncthreads();

    // per-g (tid==g): G[l] = sum_c T[l][c]*WL[c][g]; softmax over l; wo = max_l Rc*exp / S
    const int g = tid;
    float wl[19];
    #pragma unroll
    for (int c = 0; c < 19; ++c) wl[c] = WLs[c * 256 + g];

    float m = -1e30f;
    for (int l = 0; l < 128; ++l) {
        const float* tl = T + l * 20;
        float gg = 0.f;
        #pragma unroll
        for (int c = 0; c < 19; ++c) gg += tl[c] * wl[c];
        m = fmaxf(m, gg);
    }
    float S = 0.f, vmax = -1e30f;
    for (int l = 0; l < 128; ++l) {
        const float* tl = T + l * 20;
        float gg = 0.f;
        #pragma unroll
        for (int c = 0; c < 19; ++c) gg += tl[c] * wl[c];
        float e = expf(gg - m);
        S += e;
        vmax = fmaxf(vmax, Rc_s[l * 257 + g] * e);
    }
    out[(size_t)b * 256 + g] = vmax / S;
}

// ---------------------------------------------------------------------------
// Kernel D: passthrough WL into output tail
// ---------------------------------------------------------------------------
__global__ void wl_copy_kernel(const float* __restrict__ WL, float* __restrict__ out)
{
    int i = blockIdx.x * 256 + threadIdx.x;
    if (i < 19 * 256) out[512 * 256 + i] = WL[i];
}

// ---------------------------------------------------------------------------
extern "C" void kernel_launch(void* const* d_in, const int* in_sizes, int n_in,
                              void* d_out, int out_size)
{
    const int*   inputs = (const int*)d_in[0];
    const int*   e1s    = (const int*)d_in[1];
    const int*   e1e    = (const int*)d_in[2];
    const int*   e2s    = (const int*)d_in[3];
    const int*   e2e    = (const int*)d_in[4];
    const int*   p1     = (const int*)d_in[5];
    const int*   p2     = (const int*)d_in[6];
    const float* emb    = (const float*)d_in[7];
    const float* pos1   = (const float*)d_in[8];
    const float* pos2   = (const float*)d_in[9];
    const float* convw  = (const float*)d_in[10];
    const float* convb  = (const float*)d_in[11];
    const float* U      = (const float*)d_in[12];
    const float* WL     = (const float*)d_in[13];
    float* out = (float*)d_out;

    const int PREP_SMEM = 13996 * 4;    // 55984 B
    const int HEAD_SMEM = 45184 * 4;    // 180736 B
    cudaFuncSetAttribute(prep_kernel, cudaFuncAttributeMaxDynamicSharedMemorySize, PREP_SMEM);
    cudaFuncSetAttribute(head_kernel, cudaFuncAttributeMaxDynamicSharedMemorySize, HEAD_SMEM);

    prep_kernel<<<512, 256, PREP_SMEM>>>(inputs, e1s, e1e, e2s, e2e, p1, p2, emb, pos1, pos2);
    wt_kernel<<<1050, 256>>>(convw);
    conv_gemm_kernel<<<dim3(4, 512), 256>>>(convb);
    head_kernel<<<512, 256, HEAD_SMEM>>>(U, WL, out);
    wl_copy_kernel<<<19, 256>>>(WL, out);
}

// round 2
// speedup vs baseline: 1.9290x; 1.9290x over previous
#include <cuda_runtime.h>
#include <cuda_bf16.h>
#include <math.h>
#include <stdint.h>

// Problem constants:
// B=512, L=128, DIM=100, PDIM=25, WIN=3, FEAT=350, FNUM=256, LAB=19
// conv GEMM: M=512*128, N=256, K=3*350, computed as 3 taps x K=350
// bf16 split: C = Ah*Bh + Ah*Bl + Al*Bh  (9 passes of K=352-padded)

#define BF16 __nv_bfloat16

// ---------------- scratch (static device arrays; no allocations allowed) ----
__device__ BF16  g_Rh[512 * 130 * 352];   // padded R rows (352-wide), bf16 hi
__device__ BF16  g_Rl[512 * 130 * 352];   // bf16 lo residual
__device__ BF16  g_Wh[3 * 352 * 256];     // W[t][k][f] bf16 hi (k padded to 352)
__device__ BF16  g_Wl[3 * 352 * 256];     // bf16 lo
__device__ float g_Rc[512 * 128 * 256];   // tanh(conv+bias), fp32
__device__ float g_T [512 * 128 * 19];    // T = Rc . U

static __device__ __forceinline__ uint32_t smem_u32(const void* p) {
    uint32_t r;
    asm("{ .reg .u64 t; cvta.to.shared.u64 t, %1; cvt.u32.u64 %0, t; }" : "=r"(r) : "l"(p));
    return r;
}
static __device__ __forceinline__ void cp16(uint32_t dst, const void* src) {
    asm volatile("cp.async.cg.shared.global [%0], [%1], 16;" :: "r"(dst), "l"(src));
}
static __device__ __forceinline__ void mma_bf16(float* c, const uint32_t* a, uint32_t b0, uint32_t b1) {
    asm volatile(
        "mma.sync.aligned.m16n8k16.row.col.f32.bf16.bf16.f32 "
        "{%0,%1,%2,%3}, {%4,%5,%6,%7}, {%8,%9}, {%0,%1,%2,%3};"
        : "+f"(c[0]), "+f"(c[1]), "+f"(c[2]), "+f"(c[3])
        : "r"(a[0]), "r"(a[1]), "r"(a[2]), "r"(a[3]), "r"(b0), "r"(b1));
}

// ---------------------------------------------------------------------------
// Kernel A: gather embeddings, span means, dual softmax attention, build R
// writes bf16 hi/lo padded-row buffers. one block per b, 256 threads.
// ---------------------------------------------------------------------------
__global__ void prep_kernel(const int* __restrict__ inputs,
                            const int* __restrict__ e1s_, const int* __restrict__ e1e_,
                            const int* __restrict__ e2s_, const int* __restrict__ e2e_,
                            const int* __restrict__ p1, const int* __restrict__ p2,
                            const float* __restrict__ emb,
                            const float* __restrict__ pos1, const float* __restrict__ pos2)
{
    extern __shared__ float sm[];
    float* we   = sm;                   // [128][101]
    float* emb0 = sm + 12928;
    float* l1   = emb0 + 100;
    float* l2   = l1 + 100;
    float* sc1  = l2 + 100;
    float* sc2  = sc1 + 128;
    float* ine  = sc2 + 128;
    int*   ids  = (int*)(ine + 128);
    int*   q1   = ids + 128;
    int*   q2   = q1 + 128;
    __shared__ float m1s, S1s, m2s, S2s;

    const int b = blockIdx.x;
    const int tid = threadIdx.x;

    if (tid < 128) {
        ids[tid] = inputs[b * 128 + tid];
        q1[tid]  = p1[b * 128 + tid];
        q2[tid]  = p2[b * 128 + tid];
    } else if (tid < 228) {
        emb0[tid - 128] = emb[tid - 128];   // emb row 0 (pad token)
    }
    __syncthreads();

    for (int i = tid; i < 128 * 100; i += 256) {
        int l = i / 100;
        int d = i - l * 100;
        we[l * 101 + d] = emb[(long long)ids[l] * 100 + d];
    }
    __syncthreads();

    if (tid < 100) {
        int s1i = e1s_[b], e1i = e1e_[b];
        int s2i = e2s_[b], e2i = e2e_[b];
        float a = 0.f, c = 0.f;
        for (int l = s1i; l <= e1i; ++l) a += we[l * 101 + tid];
        for (int l = s2i; l <= e2i; ++l) c += we[l * 101 + tid];
        l1[tid] = a / (float)(e1i - s1i + 1);
        l2[tid] = c / (float)(e2i - s2i + 1);
    }
    __syncthreads();

    if (tid < 128) {
        float a = 0.f, c = 0.f;
        const float* w = we + tid * 101;
        #pragma unroll 4
        for (int d = 0; d < 100; ++d) { a += w[d] * l1[d]; c += w[d] * l2[d]; }
        sc1[tid] = a; sc2[tid] = c;
    }
    __syncthreads();

    if (tid < 64) {
        const float* sc = (tid < 32) ? sc1 : sc2;
        int lane = tid & 31;
        float m = -1e30f;
        for (int l = lane; l < 128; l += 32) m = fmaxf(m, sc[l]);
        for (int o = 16; o; o >>= 1) m = fmaxf(m, __shfl_xor_sync(0xffffffffu, m, o));
        float s = 0.f;
        for (int l = lane; l < 128; l += 32) s += expf(sc[l] - m);
        for (int o = 16; o; o >>= 1) s += __shfl_xor_sync(0xffffffffu, s, o);
        if (lane == 0) {
            if (tid < 32) { m1s = m; S1s = s; } else { m2s = m; S2s = s; }
        }
    }
    __syncthreads();

    if (tid < 128)
        ine[tid] = 0.5f * (expf(sc1[tid] - m1s) / S1s + expf(sc2[tid] - m2s) / S2s);
    __syncthreads();

    // write R rows (padded row l+1), cols 0..351 (350,351 zero), bf16 hi/lo
    BF16* rh = g_Rh + ((size_t)b * 130 + 1) * 352;
    BF16* rl = g_Rl + ((size_t)b * 130 + 1) * 352;
    for (int i = tid; i < 128 * 352; i += 256) {
        int l = i / 352;
        int d = i - l * 352;
        float v = 0.f;
        if (d < 350) {
            float s = ine[l];
            if (d < 300) {
                if (l != 0) {
                    int j = d / 100;
                    int dd = d - j * 100;
                    int lw = l - 1 + j;           // 0..128
                    v = ((lw < 128) ? we[lw * 101 + dd] : emb0[dd]) * s;
                }
            } else if (d < 325) {
                v = pos1[q1[l] * 25 + (d - 300)] * s;
            } else {
                v = pos2[q2[l] * 25 + (d - 325)] * s;
            }
        }
        BF16 hi = __float2bfloat16(v);
        BF16 lo = __float2bfloat16(v - __bfloat162float(hi));
        rh[(size_t)l * 352 + d] = hi;
        rl[(size_t)l * 352 + d] = lo;
    }
    // zero padding rows 0 and 129
    for (int d = tid; d < 352; d += 256) {
        BF16 z = __float2bfloat16(0.f);
        g_Rh[((size_t)b * 130) * 352 + d] = z;
        g_Rh[((size_t)b * 130 + 129) * 352 + d] = z;
        g_Rl[((size_t)b * 130) * 352 + d] = z;
        g_Rl[((size_t)b * 130 + 129) * 352 + d] = z;
    }
}

// ---------------------------------------------------------------------------
// Kernel W: split conv weights into bf16 hi/lo, layout [t][k(352)][f(256)]
// ---------------------------------------------------------------------------
__global__ void wsplit_kernel(const float* __restrict__ convw)
{
    int kk = blockIdx.x;      // 0..1055 = t*352 + k
    int f  = threadIdx.x;     // 0..255
    int t  = kk / 352;
    int k  = kk - t * 352;
    float v = (k < 350) ? convw[(size_t)f * 1050 + t * 350 + k] : 0.f;
    BF16 hi = __float2bfloat16(v);
    BF16 lo = __float2bfloat16(v - __bfloat162float(hi));
    g_Wh[(size_t)kk * 256 + f] = hi;
    g_Wl[(size_t)kk * 256 + f] = lo;
}

// ---------------------------------------------------------------------------
// Kernel B: conv as bf16x3 tensor-core GEMM + bias + tanh
// Block tile 128(M) x 128(N), BK=32, 256 threads = 8 warps (4m x 2n),
// warp tile 32x64, mma.sync m16n8k16. 9 passes x 11 chunks = 99 iters.
// ---------------------------------------------------------------------------
__device__ __forceinline__ void conv_load(int q, int b, int n0, BF16 (*As)[40], BF16 (*Bs)[136], int tid)
{
    int pass = q / 11, ch = q - pass * 11;
    int t = pass / 3, sp = pass - t * 3;
    const BF16* Ap = (sp < 2 ? g_Rh : g_Rl) + ((size_t)(b * 130 + t)) * 352 + ch * 32;
    const BF16* Bp = (sp == 1 ? g_Wl : g_Wh) + ((size_t)(t * 352 + ch * 32)) * 256 + n0;
    int am = tid >> 1, ah = (tid & 1) * 16;               // A: 128 rows x 32 cols
    cp16(smem_u32(&As[am][ah]),     Ap + (size_t)am * 352 + ah);
    cp16(smem_u32(&As[am][ah + 8]), Ap + (size_t)am * 352 + ah + 8);
    int bk = tid >> 3, bs = (tid & 7) * 16;               // B: 32 rows x 128 cols
    cp16(smem_u32(&Bs[bk][bs]),     Bp + (size_t)bk * 256 + bs);
    cp16(smem_u32(&Bs[bk][bs + 8]), Bp + (size_t)bk * 256 + bs + 8);
}

__global__ __launch_bounds__(256, 2) void conv_mma_kernel(const float* __restrict__ convb)
{
    __shared__ BF16 As[2][128][40];   // rows padded to 80B: conflict-free ldmatrix
    __shared__ BF16 Bs[2][32][136];   // rows padded to 272B

    const int b   = blockIdx.y;
    const int n0  = blockIdx.x * 128;
    const int tid = threadIdx.x;
    const int lane = tid & 31;
    const int wid  = tid >> 5;
    const int wm = wid >> 1;          // 0..3
    const int wn = wid & 1;           // 0..1

    float acc[2][8][4];
    #pragma unroll
    for (int s = 0; s < 2; ++s)
        #pragma unroll
        for (int j = 0; j < 8; ++j)
            #pragma unroll
            for (int x = 0; x < 4; ++x) acc[s][j][x] = 0.f;

    conv_load(0, b, n0, As[0], Bs[0], tid);
    asm volatile("cp.async.commit_group;");

    for (int q = 0; q < 99; ++q) {
        asm volatile("cp.async.wait_group 0;");
        __syncthreads();
        if (q + 1 < 99) {
            conv_load(q + 1, b, n0, As[(q + 1) & 1], Bs[(q + 1) & 1], tid);
            asm volatile("cp.async.commit_group;");
        }
        BF16 (*A)[40]  = As[q & 1];
        BF16 (*Bb)[136] = Bs[q & 1];

        #pragma unroll
        for (int ks = 0; ks < 2; ++ks) {
            uint32_t a[2][4];
            #pragma unroll
            for (int s = 0; s < 2; ++s) {
                uint32_t addr = smem_u32(&A[wm * 32 + s * 16 + (lane & 15)][ks * 16 + (lane >> 4) * 8]);
                asm volatile("ldmatrix.sync.aligned.m8n8.x4.shared.b16 {%0,%1,%2,%3}, [%4];"
                             : "=r"(a[s][0]), "=r"(a[s][1]), "=r"(a[s][2]), "=r"(a[s][3]) : "r"(addr));
            }
            #pragma unroll
            for (int i = 0; i < 4; ++i) {
                uint32_t bb[4];
                uint32_t addr = smem_u32(&Bb[ks * 16 + (lane & 7) + ((lane >> 3) & 1) * 8]
                                           [wn * 64 + i * 16 + (lane >> 4) * 8]);
                asm volatile("ldmatrix.sync.aligned.m8n8.x4.trans.shared.b16 {%0,%1,%2,%3}, [%4];"
                             : "=r"(bb[0]), "=r"(bb[1]), "=r"(bb[2]), "=r"(bb[3]) : "r"(addr));
                #pragma unroll
                for (int s = 0; s < 2; ++s) {
                    mma_bf16(acc[s][2 * i],     a[s], bb[0], bb[1]);
                    mma_bf16(acc[s][2 * i + 1], a[s], bb[2], bb[3]);
                }
            }
        }
        __syncthreads();
    }

    // epilogue: bias + tanh -> g_Rc fp32
    const int col_base = n0 + wn * 64 + (lane & 3) * 2;
    float bias[8][2];
    #pragma unroll
    for (int j = 0; j < 8; ++j) {
        bias[j][0] = __ldg(convb + col_base + j * 8);
        bias[j][1] = __ldg(convb + col_base + j * 8 + 1);
    }
    #pragma unroll
    for (int s = 0; s < 2; ++s) {
        int row = b * 128 + wm * 32 + s * 16 + (lane >> 2);
        #pragma unroll
        for (int j = 0; j < 8; ++j) {
            int col = col_base + j * 8;
            g_Rc[(size_t)row * 256 + col]            = tanhf(acc[s][j][0] + bias[j][0]);
            g_Rc[(size_t)row * 256 + col + 1]        = tanhf(acc[s][j][1] + bias[j][1]);
            g_Rc[(size_t)(row + 8) * 256 + col]      = tanhf(acc[s][j][2] + bias[j][0]);
            g_Rc[(size_t)(row + 8) * 256 + col + 1]  = tanhf(acc[s][j][3] + bias[j][1]);
        }
    }
}

// ---------------------------------------------------------------------------
// Kernel C1: T[b][l][c] = sum_f Rc[b][l][f] * U[f][c]
// warp handles 4 rows (l); lanes split f; shfl reduce. grid (4, 512) x 256.
// ---------------------------------------------------------------------------
__global__ __launch_bounds__(256) void t_kernel(const float* __restrict__ U)
{
    __shared__ float Us[4864];
    const int tid = threadIdx.x;
    for (int i = tid; i < 4864; i += 256) Us[i] = U[i];
    __syncthreads();

    const int lane = tid & 31, w = tid >> 5;
    const int b = blockIdx.y;
    const int l0 = blockIdx.x * 32 + w * 4;
    const float* rc = g_Rc + ((size_t)b * 128 + l0) * 256;

    float acc[4][19];
    #pragma unroll
    for (int j = 0; j < 4; ++j)
        #pragma unroll
        for (int c = 0; c < 19; ++c) acc[j][c] = 0.f;

    for (int r = 0; r < 8; ++r) {
        int f = lane + 32 * r;
        float a0 = rc[f];
        float a1 = rc[256 + f];
        float a2 = rc[512 + f];
        float a3 = rc[768 + f];
        const float* up = Us + f * 19;
        #pragma unroll
        for (int c = 0; c < 19; ++c) {
            float u = up[c];
            acc[0][c] += a0 * u;
            acc[1][c] += a1 * u;
            acc[2][c] += a2 * u;
            acc[3][c] += a3 * u;
        }
    }
    #pragma unroll
    for (int j = 0; j < 4; ++j)
        #pragma unroll
        for (int c = 0; c < 19; ++c) {
            float v = acc[j][c];
            #pragma unroll
            for (int o = 16; o; o >>= 1) v += __shfl_xor_sync(0xffffffffu, v, o);
            if (lane == c) g_T[((size_t)b * 128 + l0 + j) * 19 + c] = v;
        }
}

// ---------------------------------------------------------------------------
// Kernel C2: G = T.WL, online softmax over l, wo[g] = max_l Rc*softG
// block per b, thread per g, T broadcast from smem. Single pass over l.
// ---------------------------------------------------------------------------
__global__ __launch_bounds__(256) void head2_kernel(const float* __restrict__ WL,
                                                    float* __restrict__ out)
{
    __shared__ float Ts[128 * 20];
    const int tid = threadIdx.x, b = blockIdx.x;
    const float* tg = g_T + (size_t)b * 128 * 19;
    for (int i = tid; i < 2432; i += 256) {
        int l = i / 19, c = i - l * 19;
        Ts[l * 20 + c] = tg[i];
    }
    __syncthreads();

    const int g = tid;
    float wl[19];
    #pragma unroll
    for (int c = 0; c < 19; ++c) wl[c] = WL[c * 256 + g];

    const float* rcg = g_Rc + (size_t)b * 128 * 256 + g;

    // seed with l = 0
    float m = 0.f;
    #pragma unroll
    for (int c = 0; c < 19; ++c) m += Ts[c] * wl[c];
    float S = 1.f;
    float vmax = rcg[0];

    for (int l = 1; l < 128; ++l) {
        const float* tl = Ts + l * 20;
        float g2 = 0.f;
        #pragma unroll
        for (int c = 0; c < 19; ++c) g2 += tl[c] * wl[c];
        float rc = rcg[(size_t)l * 256];
        float m2 = fmaxf(m, g2);
        float c1 = __expf(m - m2);
        float c2 = __expf(g2 - m2);
        S = S * c1 + c2;
        vmax = fmaxf(vmax * c1, rc * c2);
        m = m2;
    }
    out[(size_t)b * 256 + g] = vmax / S;
}

// ---------------------------------------------------------------------------
__global__ void wl_copy_kernel(const float* __restrict__ WL, float* __restrict__ out)
{
    int i = blockIdx.x * 256 + threadIdx.x;
    if (i < 19 * 256) out[512 * 256 + i] = WL[i];
}

// ---------------------------------------------------------------------------
extern "C" void kernel_launch(void* const* d_in, const int* in_sizes, int n_in,
                              void* d_out, int out_size)
{
    const int*   inputs = (const int*)d_in[0];
    const int*   e1s    = (const int*)d_in[1];
    const int*   e1e    = (const int*)d_in[2];
    const int*   e2s    = (const int*)d_in[3];
    const int*   e2e    = (const int*)d_in[4];
    const int*   p1     = (const int*)d_in[5];
    const int*   p2     = (const int*)d_in[6];
    const float* emb    = (const float*)d_in[7];
    const float* pos1   = (const float*)d_in[8];
    const float* pos2   = (const float*)d_in[9];
    const float* convw  = (const float*)d_in[10];
    const float* convb  = (const float*)d_in[11];
    const float* U      = (const float*)d_in[12];
    const float* WL     = (const float*)d_in[13];
    float* out = (float*)d_out;

    const int PREP_SMEM = 13996 * 4;    // 55984 B
    cudaFuncSetAttribute(prep_kernel, cudaFuncAttributeMaxDynamicSharedMemorySize, PREP_SMEM);

    prep_kernel<<<512, 256, PREP_SMEM>>>(inputs, e1s, e1e, e2s, e2e, p1, p2, emb, pos1, pos2);
    wsplit_kernel<<<1056, 256>>>(convw);
    conv_mma_kernel<<<dim3(2, 512), 256>>>(convb);
    t_kernel<<<dim3(4, 512), 256>>>(U);
    head2_kernel<<<512, 256>>>(WL, out);
    wl_copy_kernel<<<19, 256>>>(WL, out);
}